// round 15
// baseline (speedup 1.0000x reference)
#include <cuda_runtime.h>
#include <math.h>
#include <float.h>
#include <stdint.h>

#define NN 100000
#define NE 800000
#define NG 64
#define NSCAN_BLK 98   // ceil(NN/1024)

// ---------------- scratch pool (device globals; resolved device-side) ----------------
__device__ float g_B0[NN * 192];   // x1_res
__device__ float g_B1[NN * 192];   // agg (gather target)
__device__ float g_B2[NN * 256];   // h -> c -> tmp -> t
__device__ float g_B3[NN * 192];   // hw -> gate -> t2
__device__ float g_B4[NN * 192];   // h2 -> z
__device__ float g_B5[NN * 192];   // c2 -> z1_res
__device__ float g_dinv[NN];
__device__ float g_small[2 * NG * 192];  // zg | zgw
__device__ int   g_rowptr[NN + 1];
__device__ int   g_pos[NN];
__device__ int   g_bsum[128];
__device__ int   g_gstart[NG + 1];
__device__ int   g_csrc[NE];

#define SEL_ZG   16
#define SEL_ZGW  19

__device__ __forceinline__ float* scratch(int id) {
    switch (id) {
        case 0:  return g_B0;
        case 1:  return g_B1;
        case 2:  return g_B2;
        case 3:  return g_B3;
        case 4:  return g_B4;
        case 5:  return g_B5;
        case SEL_ZG:   return g_small;
        case SEL_ZGW:  return g_small + NG * 192;
        default: return nullptr;
    }
}

// ---------------- CSR build (round-6 exact) ----------------
__global__ void zero_pos_kernel() {
    int i = blockIdx.x * blockDim.x + threadIdx.x;
    if (i < NN) g_pos[i] = 0;
}

__global__ void gstart_kernel(const int* __restrict__ batch) {
    int g = threadIdx.x;
    if (g > NG) return;
    int lo = 0, hi = NN;
    while (lo < hi) {
        int mid = (lo + hi) >> 1;
        if (batch[mid] < g) lo = mid + 1; else hi = mid;
    }
    g_gstart[g] = lo;
}

__global__ void count_deg_kernel(const int* __restrict__ dst) {
    int e = blockIdx.x * blockDim.x + threadIdx.x;
    if (e < NE) atomicAdd(&g_pos[dst[e]], 1);
}

__global__ void dinv_kernel() {
    int i = blockIdx.x * blockDim.x + threadIdx.x;
    if (i < NN) g_dinv[i] = rsqrtf((float)g_pos[i] + 1.0f);
}

__global__ void scan1_kernel() {
    __shared__ int s[1024];
    int tid = threadIdx.x;
    int idx = blockIdx.x * 1024 + tid;
    int v = (idx < NN) ? g_pos[idx] : 0;
    s[tid] = v;
    __syncthreads();
    for (int off = 1; off < 1024; off <<= 1) {
        int t = (tid >= off) ? s[tid - off] : 0;
        __syncthreads();
        s[tid] += t;
        __syncthreads();
    }
    if (idx < NN) g_rowptr[idx] = s[tid] - v;
    if (tid == 1023) g_bsum[blockIdx.x] = s[1023];
}

__global__ void scan2_kernel() {
    __shared__ int s[128];
    int tid = threadIdx.x;
    int v = (tid < NSCAN_BLK) ? g_bsum[tid] : 0;
    s[tid] = v;
    __syncthreads();
    for (int off = 1; off < 128; off <<= 1) {
        int t = (tid >= off) ? s[tid - off] : 0;
        __syncthreads();
        s[tid] += t;
        __syncthreads();
    }
    if (tid < NSCAN_BLK) g_bsum[tid] = s[tid] - v;
    if (tid == 127) g_rowptr[NN] = s[127];
}

__global__ void scan3_kernel() {
    int idx = blockIdx.x * 1024 + threadIdx.x;
    if (idx < NN) {
        int r = g_rowptr[idx] + g_bsum[blockIdx.x];
        g_rowptr[idx] = r;
        g_pos[idx] = r;
    }
}

__global__ void csr_fill_kernel(const int* __restrict__ src, const int* __restrict__ dst) {
    int e = blockIdx.x * blockDim.x + threadIdx.x;
    if (e >= NE) return;
    int p = atomicAdd(&g_pos[dst[e]], 1);
    g_csrc[p] = src[e];
}

// ---------------- gather kernels (CSR, no atomics; 4x-coarsened) ----------------
// D=192: 12 threads/node, each accumulates chunks t, t+12, t+24, t+36 (float4 units).
__global__ void gather_add192_kernel(int xSel, const float* __restrict__ pe,
                                     int aggSel, int total) {
    int tid = blockIdx.x * blockDim.x + threadIdx.x;
    if (tid >= total) return;
    const float* x = scratch(xSel);
    float* agg = scratch(aggSel);
    int i = tid / 12;
    int t = tid - i * 12;
    int c0 = t * 4, c1 = (t + 12) * 4, c2 = (t + 24) * 4, c3 = (t + 36) * 4;
    int p0 = c0 & 63, p1 = c1 & 63, p2 = c2 & 63, p3 = c3 & 63;
    int beg = g_rowptr[i], end = g_rowptr[i + 1];
    float4 a0 = make_float4(0.f, 0.f, 0.f, 0.f), a1 = a0, a2 = a0, a3 = a0;
    for (int e = beg; e < end; e++) {
        int s = g_csrc[e];
        const float* xr = x + (size_t)s * 192;
        float4 v0 = *(const float4*)(xr + c0);
        float4 v1 = *(const float4*)(xr + c1);
        float4 v2 = *(const float4*)(xr + c2);
        float4 v3 = *(const float4*)(xr + c3);
        if (pe) {
            const float* pr = pe + (size_t)s * 64;
            float4 q0 = *(const float4*)(pr + p0);
            float4 q1 = *(const float4*)(pr + p1);
            float4 q2 = *(const float4*)(pr + p2);
            float4 q3 = *(const float4*)(pr + p3);
            v0.x += q0.x; v0.y += q0.y; v0.z += q0.z; v0.w += q0.w;
            v1.x += q1.x; v1.y += q1.y; v1.z += q1.z; v1.w += q1.w;
            v2.x += q2.x; v2.y += q2.y; v2.z += q2.z; v2.w += q2.w;
            v3.x += q3.x; v3.y += q3.y; v3.z += q3.z; v3.w += q3.w;
        }
        a0.x += v0.x; a0.y += v0.y; a0.z += v0.z; a0.w += v0.w;
        a1.x += v1.x; a1.y += v1.y; a1.z += v1.z; a1.w += v1.w;
        a2.x += v2.x; a2.y += v2.y; a2.z += v2.z; a2.w += v2.w;
        a3.x += v3.x; a3.y += v3.y; a3.z += v3.z; a3.w += v3.w;
    }
    float* ar = agg + (size_t)i * 192;
    *(float4*)(ar + c0) = a0;
    *(float4*)(ar + c1) = a1;
    *(float4*)(ar + c2) = a2;
    *(float4*)(ar + c3) = a3;
}

// D=32: 4 threads/node, each accumulates chunks t, t+4 (float4 units).
__global__ void gather_add32_kernel(const float* __restrict__ x, int aggSel, int total) {
    int tid = blockIdx.x * blockDim.x + threadIdx.x;
    if (tid >= total) return;
    float* agg = scratch(aggSel);
    int i = tid >> 2;
    int t = tid & 3;
    int c0 = t * 4, c1 = (t + 4) * 4;
    int beg = g_rowptr[i], end = g_rowptr[i + 1];
    float4 a0 = make_float4(0.f, 0.f, 0.f, 0.f), a1 = a0;
    for (int e = beg; e < end; e++) {
        int s = g_csrc[e];
        const float* xr = x + (size_t)s * 32;
        float4 v0 = *(const float4*)(xr + c0);
        float4 v1 = *(const float4*)(xr + c1);
        a0.x += v0.x; a0.y += v0.y; a0.z += v0.z; a0.w += v0.w;
        a1.x += v1.x; a1.y += v1.y; a1.z += v1.z; a1.w += v1.w;
    }
    float* ar = agg + (size_t)i * 32;
    *(float4*)(ar + c0) = a0;
    *(float4*)(ar + c1) = a1;
}

// fused GCN (coarsened): out = relu(dinv[i]*sum(hw[s]*dinv[s]) + hw[i]*dinv[i]^2 + b)
// [+ add1 + add2]
__global__ void gather_gcn_kernel(int hwSel, const float* __restrict__ b,
                                  int outSel, int add1Sel, int add2Sel, int total) {
    int tid = blockIdx.x * blockDim.x + threadIdx.x;
    if (tid >= total) return;
    const float* hw = scratch(hwSel);
    float* out = scratch(outSel);
    int i = tid / 12;
    int t = tid - i * 12;
    int beg = g_rowptr[i], end = g_rowptr[i + 1];
    float4 a[4];
#pragma unroll
    for (int j = 0; j < 4; j++) a[j] = make_float4(0.f, 0.f, 0.f, 0.f);
    for (int e = beg; e < end; e++) {
        int s = g_csrc[e];
        float w = g_dinv[s];
        const float* hr = hw + (size_t)s * 192;
#pragma unroll
        for (int j = 0; j < 4; j++) {
            float4 v = *(const float4*)(hr + (t + 12 * j) * 4);
            a[j].x += v.x * w; a[j].y += v.y * w; a[j].z += v.z * w; a[j].w += v.w * w;
        }
    }
    float di = g_dinv[i];
    float dii = di * di;
#pragma unroll
    for (int j = 0; j < 4; j++) {
        int c = (t + 12 * j) * 4;
        size_t idx = (size_t)i * 192 + c;
        float4 sv = *(const float4*)(hw + idx);
        float4 bb = *(const float4*)(b + c);
        float4 o;
        o.x = fmaxf(a[j].x * di + sv.x * dii + bb.x, 0.f);
        o.y = fmaxf(a[j].y * di + sv.y * dii + bb.y, 0.f);
        o.z = fmaxf(a[j].z * di + sv.z * dii + bb.z, 0.f);
        o.w = fmaxf(a[j].w * di + sv.w * dii + bb.w, 0.f);
        if (add1Sel >= 0) {
            float4 x1 = *(const float4*)(scratch(add1Sel) + idx);
            float4 x2 = *(const float4*)(scratch(add2Sel) + idx);
            o.x += x1.x + x2.x; o.y += x1.y + x2.y;
            o.z += x1.z + x2.z; o.w += x1.w + x2.w;
        }
        *(float4*)(out + idx) = o;
    }
}

__global__ void gather_gcn_bcast_kernel(int zgwSel, const int* __restrict__ batch,
                                        const float* __restrict__ b,
                                        int outSel, int total) {
    int tid = blockIdx.x * blockDim.x + threadIdx.x;
    if (tid >= total) return;
    const float* zgw = scratch(zgwSel);
    float* out = scratch(outSel);
    int i = tid / 12;
    int t = tid - i * 12;
    int beg = g_rowptr[i], end = g_rowptr[i + 1];
    float4 a[4];
#pragma unroll
    for (int j = 0; j < 4; j++) a[j] = make_float4(0.f, 0.f, 0.f, 0.f);
    for (int e = beg; e < end; e++) {
        int s = g_csrc[e];
        float w = g_dinv[s];
        const float* zr = zgw + (size_t)batch[s] * 192;
#pragma unroll
        for (int j = 0; j < 4; j++) {
            float4 v = *(const float4*)(zr + (t + 12 * j) * 4);
            a[j].x += v.x * w; a[j].y += v.y * w; a[j].z += v.z * w; a[j].w += v.w * w;
        }
    }
    float di = g_dinv[i];
    float dii = di * di;
    const float* zr = zgw + (size_t)batch[i] * 192;
#pragma unroll
    for (int j = 0; j < 4; j++) {
        int c = (t + 12 * j) * 4;
        float4 sv = *(const float4*)(zr + c);
        float4 bb = *(const float4*)(b + c);
        float4 o;
        o.x = fmaxf(a[j].x * di + sv.x * dii + bb.x, 0.f);
        o.y = fmaxf(a[j].y * di + sv.y * dii + bb.y, 0.f);
        o.z = fmaxf(a[j].z * di + sv.z * dii + bb.z, 0.f);
        o.w = fmaxf(a[j].w * di + sv.w * dii + bb.w, 0.f);
        *(float4*)(out + (size_t)i * 192 + c) = o;
    }
}

// ---------------- fused attention: one block per graph, thread = feature ----------------
__global__ void att_fused_kernel(int gateSel, int zSel) {
    int gph = blockIdx.x;
    int f = threadIdx.x;   // 0..191
    const float* gate = scratch(gateSel);
    const float* z = scratch(zSel);
    float* zg = scratch(SEL_ZG);
    int n0 = g_gstart[gph], n1 = g_gstart[gph + 1];
    if (n0 >= n1) { zg[gph * 192 + f] = 0.f; return; }

    float m0 = -FLT_MAX, m1 = -FLT_MAX, m2 = -FLT_MAX, m3 = -FLT_MAX;
    int n = n0;
    for (; n + 3 < n1; n += 4) {
        m0 = fmaxf(m0, gate[(size_t)(n + 0) * 192 + f]);
        m1 = fmaxf(m1, gate[(size_t)(n + 1) * 192 + f]);
        m2 = fmaxf(m2, gate[(size_t)(n + 2) * 192 + f]);
        m3 = fmaxf(m3, gate[(size_t)(n + 3) * 192 + f]);
    }
    for (; n < n1; n++) m0 = fmaxf(m0, gate[(size_t)n * 192 + f]);
    float m = fmaxf(fmaxf(m0, m1), fmaxf(m2, m3));

    float es0 = 0.f, es1 = 0.f, ez0 = 0.f, ez1 = 0.f;
    n = n0;
    for (; n + 1 < n1; n += 2) {
        size_t i0 = (size_t)n * 192 + f, i1 = (size_t)(n + 1) * 192 + f;
        float e0 = expf(gate[i0] - m);
        float e1 = expf(gate[i1] - m);
        es0 += e0; ez0 += e0 * z[i0];
        es1 += e1; ez1 += e1 * z[i1];
    }
    if (n < n1) {
        size_t i0 = (size_t)n * 192 + f;
        float e0 = expf(gate[i0] - m);
        es0 += e0; ez0 += e0 * z[i0];
    }
    zg[gph * 192 + f] = (ez0 + ez1) / (es0 + es1);
}

// ---------------- TF32 tensor-core GEMM (round-6 exact: BM=256, single-buffered) ----
__device__ __forceinline__ uint32_t f2tf(float f) {
    uint32_t u;
    asm("cvt.rna.tf32.f32 %0, %1;" : "=r"(u) : "f"(f));
    return u;
}

__device__ __forceinline__ void mma_tf32(float& c0, float& c1, float& c2, float& c3,
                                         uint32_t a0, uint32_t a1, uint32_t a2, uint32_t a3,
                                         uint32_t b0, uint32_t b1) {
    asm volatile(
        "mma.sync.aligned.m16n8k8.row.col.f32.tf32.tf32.f32 "
        "{%0,%1,%2,%3},{%4,%5,%6,%7},{%8,%9},{%0,%1,%2,%3};\n"
        : "+f"(c0), "+f"(c1), "+f"(c2), "+f"(c3)
        : "r"(a0), "r"(a1), "r"(a2), "r"(a3), "r"(b0), "r"(b1));
}

__global__ __launch_bounds__(256)
void tgemm_kernel(int M, int N, int K,
                  const float* __restrict__ Aext, int Asel,
                  const float* __restrict__ B,
                  const float* __restrict__ bias,
                  int resSel,
                  float* __restrict__ Cext, int Csel,
                  int relu) {
    __shared__ uint32_t As[256][20];  // [m][k], stride 20 -> conflict-free frag loads
    __shared__ uint32_t Bs[16][72];   // [k][n], stride 72 -> conflict-free frag loads

    const float* A = Aext ? Aext : scratch(Asel);
    float* C = Cext ? Cext : scratch(Csel);
    const float* res = (resSel >= 0) ? scratch(resSel) : nullptr;

    int tid = threadIdx.x;
    int bm0 = blockIdx.y * 256, bn0 = blockIdx.x * 64;
    int lane = tid & 31, wid = tid >> 5;
    int g = lane >> 2, t4 = lane & 3;
    int wm = (wid & 3) * 64;    // 4 warps down M
    int wn = (wid >> 2) * 32;   // 2 warps across N

    int aRow[4], aCol[4];
    bool aOk[4];
#pragma unroll
    for (int q = 0; q < 4; q++) {
        int fid = tid + 256 * q;
        aRow[q] = fid >> 2;
        aCol[q] = (fid & 3) << 2;
        aOk[q] = (bm0 + aRow[q]) < M;
    }
    int bRow = tid >> 4, bCol = (tid & 15) << 2;
    const float* Bptr = B + (size_t)bRow * N + bn0 + bCol;

    float acc[4][4][4];
#pragma unroll
    for (int mi = 0; mi < 4; mi++)
#pragma unroll
        for (int ni = 0; ni < 4; ni++)
#pragma unroll
            for (int q = 0; q < 4; q++) acc[mi][ni][q] = 0.f;

    float4 pa[4];
#pragma unroll
    for (int q = 0; q < 4; q++) {
        pa[q] = make_float4(0.f, 0.f, 0.f, 0.f);
        if (aOk[q]) pa[q] = *(const float4*)(A + (size_t)(bm0 + aRow[q]) * K + aCol[q]);
    }
    float4 pb = *(const float4*)Bptr;

    for (int k0 = 0; k0 < K; k0 += 16) {
#pragma unroll
        for (int q = 0; q < 4; q++) {
            As[aRow[q]][aCol[q] + 0] = f2tf(pa[q].x);
            As[aRow[q]][aCol[q] + 1] = f2tf(pa[q].y);
            As[aRow[q]][aCol[q] + 2] = f2tf(pa[q].z);
            As[aRow[q]][aCol[q] + 3] = f2tf(pa[q].w);
        }
        Bs[bRow][bCol + 0] = f2tf(pb.x); Bs[bRow][bCol + 1] = f2tf(pb.y);
        Bs[bRow][bCol + 2] = f2tf(pb.z); Bs[bRow][bCol + 3] = f2tf(pb.w);
        __syncthreads();

        if (k0 + 16 < K) {
#pragma unroll
            for (int q = 0; q < 4; q++)
                if (aOk[q]) pa[q] = *(const float4*)(A + (size_t)(bm0 + aRow[q]) * K + k0 + 16 + aCol[q]);
            pb = *(const float4*)(Bptr + (size_t)(k0 + 16) * N);
        }

#pragma unroll
        for (int ks = 0; ks < 16; ks += 8) {
            uint32_t af[4][4], bf[4][2];
#pragma unroll
            for (int mi = 0; mi < 4; mi++) {
                int rb = wm + mi * 16;
                af[mi][0] = As[rb + g][ks + t4];
                af[mi][1] = As[rb + g + 8][ks + t4];
                af[mi][2] = As[rb + g][ks + t4 + 4];
                af[mi][3] = As[rb + g + 8][ks + t4 + 4];
            }
#pragma unroll
            for (int ni = 0; ni < 4; ni++) {
                int cb = wn + ni * 8 + g;
                bf[ni][0] = Bs[ks + t4][cb];
                bf[ni][1] = Bs[ks + t4 + 4][cb];
            }
#pragma unroll
            for (int mi = 0; mi < 4; mi++)
#pragma unroll
                for (int ni = 0; ni < 4; ni++)
                    mma_tf32(acc[mi][ni][0], acc[mi][ni][1], acc[mi][ni][2], acc[mi][ni][3],
                             af[mi][0], af[mi][1], af[mi][2], af[mi][3],
                             bf[ni][0], bf[ni][1]);
        }
        __syncthreads();
    }

#pragma unroll
    for (int mi = 0; mi < 4; mi++) {
#pragma unroll
        for (int ni = 0; ni < 4; ni++) {
            int col = bn0 + wn + ni * 8 + 2 * t4;
            float bx = bias ? bias[col] : 0.f;
            float by = bias ? bias[col + 1] : 0.f;
#pragma unroll
            for (int h = 0; h < 2; h++) {
                int r = bm0 + wm + mi * 16 + g + h * 8;
                if (r >= M) continue;
                float v0 = acc[mi][ni][2 * h + 0] + bx;
                float v1 = acc[mi][ni][2 * h + 1] + by;
                if (relu) { v0 = fmaxf(v0, 0.f); v1 = fmaxf(v1, 0.f); }
                if (res) {
                    v0 += res[(size_t)r * N + col];
                    v1 += res[(size_t)r * N + col + 1];
                }
                *(float2*)(C + (size_t)r * N + col) = make_float2(v0, v1);
            }
        }
    }
}

// ---------------- launch helpers ----------------
static inline void launch_gemm(int M, int N, int K,
                               const float* Aext, int Asel, const float* B,
                               const float* bias, int resSel,
                               float* Cext, int Csel, int relu) {
    dim3 grid((N + 63) / 64, (M + 255) / 256);
    tgemm_kernel<<<grid, 256>>>(M, N, K, Aext, Asel, B, bias, resSel, Cext, Csel, relu);
}

extern "C" void kernel_launch(void* const* d_in, const int* in_sizes, int n_in,
                              void* d_out, int out_size) {
    const float* x1    = (const float*)d_in[0];
    const float* x2    = (const float*)d_in[1];
    const float* pe    = (const float*)d_in[2];
    const int*   ei    = (const int*)d_in[3];
    const int*   batch = (const int*)d_in[4];
    const float *Wc  = (const float*)d_in[5],  *bc  = (const float*)d_in[6];
    const float *Wmf = (const float*)d_in[7],  *bmf = (const float*)d_in[8];
    const float *Wgf = (const float*)d_in[9],  *bgf = (const float*)d_in[10];
    const float *Wmc = (const float*)d_in[11], *bmc = (const float*)d_in[12];
    const float *Wgc = (const float*)d_in[13], *bgc = (const float*)d_in[14];
    const float *Wa1 = (const float*)d_in[15], *ba1 = (const float*)d_in[16];
    const float *Wa2 = (const float*)d_in[17], *ba2 = (const float*)d_in[18];
    const float *Wgd = (const float*)d_in[19], *bgd = (const float*)d_in[20];
    const float *Wd1 = (const float*)d_in[21], *bd1 = (const float*)d_in[22];
    const float *Wd2 = (const float*)d_in[23], *bd2 = (const float*)d_in[24];
    const float *Wd3 = (const float*)d_in[25], *bd3 = (const float*)d_in[26];
    float* out = (float*)d_out;

    const int* src = ei;
    const int* dst = ei + NE;

    const int NODE192 = NN * 12;   // 12 threads/node (4x coarsened)
    const int NODE32  = NN * 4;    // 4 threads/node
    const int BLK = 256;

    // ---- CSR build + graph segment bounds (round-6 exact) ----
    zero_pos_kernel<<<(NN + BLK - 1) / BLK, BLK>>>();
    gstart_kernel<<<1, NG + 1>>>(batch);
    count_deg_kernel<<<(NE + BLK - 1) / BLK, BLK>>>(dst);
    dinv_kernel<<<(NN + BLK - 1) / BLK, BLK>>>();
    scan1_kernel<<<NSCAN_BLK, 1024>>>();
    scan2_kernel<<<1, 128>>>();
    scan3_kernel<<<NSCAN_BLK, 1024>>>();
    csr_fill_kernel<<<(NE + BLK - 1) / BLK, BLK>>>(src, dst);

    // ---- encoder ----
    launch_gemm(NN, 192, 384, x1, -1, Wc, bc, -1, nullptr, 0, 1);
    gather_add192_kernel<<<(NODE192 + BLK - 1) / BLK, BLK>>>(0, pe, 1, NODE192);
    launch_gemm(NN, 256, 192, nullptr, 1, Wmf, bmf, -1, nullptr, 2, 1);
    launch_gemm(NN, 192, 256, nullptr, 2, Wgf, nullptr, -1, nullptr, 3, 0);
    gather_gcn_kernel<<<(NODE192 + BLK - 1) / BLK, BLK>>>(3, bgf, 4, -1, -1, NODE192);
    gather_add32_kernel<<<(NODE32 + BLK - 1) / BLK, BLK>>>(x2, 1, NODE32);
    launch_gemm(NN, 64, 32, nullptr, 1, Wmc, bmc, -1, nullptr, 2, 1);
    launch_gemm(NN, 192, 64, nullptr, 2, Wgc, nullptr, -1, nullptr, 3, 0);
    // z = relu(gcn_c) + h2 + x1res  (fused) -> B4
    gather_gcn_kernel<<<(NODE192 + BLK - 1) / BLK, BLK>>>(3, bgc, 4, 4, 0, NODE192);

    // ---- attentional aggregation (atomic-free) ----
    launch_gemm(NN, 256, 192, nullptr, 4, Wa1, ba1, -1, nullptr, 2, 1);
    launch_gemm(NN, 192, 256, nullptr, 2, Wa2, ba2, -1, nullptr, 3, 0);
    att_fused_kernel<<<NG, 192>>>(3, 4);

    // ---- decoder ----
    launch_gemm(NG, 192, 192, nullptr, SEL_ZG, Wgd, nullptr, -1, nullptr, SEL_ZGW, 0);
    gather_gcn_bcast_kernel<<<(NODE192 + BLK - 1) / BLK, BLK>>>(SEL_ZGW, batch, bgd, 5, NODE192);
    gather_add192_kernel<<<(NODE192 + BLK - 1) / BLK, BLK>>>(5, pe, 1, NODE192);
    launch_gemm(NN, 192, 192, nullptr, 1, Wd1, bd1, -1, nullptr, 2, 1);
    gather_add192_kernel<<<(NODE192 + BLK - 1) / BLK, BLK>>>(2, nullptr, 1, NODE192);
    launch_gemm(NN, 192, 192, nullptr, 1, Wd2, bd2, 5, nullptr, 3, 1);
    gather_add192_kernel<<<(NODE192 + BLK - 1) / BLK, BLK>>>(3, nullptr, 1, NODE192);
    launch_gemm(NN, 384, 192, nullptr, 1, Wd3, bd3, -1, out, -1, 1);
}

// round 16
// speedup vs baseline: 1.0992x; 1.0992x over previous
#include <cuda_runtime.h>
#include <cuda_fp16.h>
#include <math.h>
#include <float.h>
#include <stdint.h>

#define NN 100000
#define NE 800000
#define NG 64
#define NSCAN_BLK 98   // ceil(NN/1024)

// ---------------- scratch pool (device globals; resolved device-side) ----------------
__device__ float g_B0[NN * 192];   // x1_res
__device__ float g_B1[NN * 192];   // agg (gather target)
__device__ float g_B2[NN * 256];   // h -> c -> tmp -> t
__device__ float g_B3[NN * 192];   // hw -> gate -> t2
__device__ float g_B4[NN * 192];   // h2 -> z
__device__ float g_B5[NN * 192];   // c2 -> z1_res
__device__ float g_dinv[NN];
__device__ float g_small[2 * NG * 192];  // zg | zgw
__device__ int   g_rowptr[NN + 1];
__device__ int   g_pos[NN];
__device__ int   g_bsum[128];
__device__ int   g_gstart[NG + 1];
__device__ int   g_csrc[NE];

#define SEL_ZG   16
#define SEL_ZGW  19

__device__ __forceinline__ float* scratch(int id) {
    switch (id) {
        case 0:  return g_B0;
        case 1:  return g_B1;
        case 2:  return g_B2;
        case 3:  return g_B3;
        case 4:  return g_B4;
        case 5:  return g_B5;
        case SEL_ZG:   return g_small;
        case SEL_ZGW:  return g_small + NG * 192;
        default: return nullptr;
    }
}

// ---------------- CSR build ----------------
__global__ void zero_pos_kernel() {
    int i = blockIdx.x * blockDim.x + threadIdx.x;
    if (i < NN) g_pos[i] = 0;
}

__global__ void gstart_kernel(const int* __restrict__ batch) {
    int g = threadIdx.x;
    if (g > NG) return;
    int lo = 0, hi = NN;
    while (lo < hi) {
        int mid = (lo + hi) >> 1;
        if (batch[mid] < g) lo = mid + 1; else hi = mid;
    }
    g_gstart[g] = lo;
}

__global__ void count_deg_kernel(const int* __restrict__ dst) {
    int e = blockIdx.x * blockDim.x + threadIdx.x;
    if (e < NE) atomicAdd(&g_pos[dst[e]], 1);
}

__global__ void dinv_kernel() {
    int i = blockIdx.x * blockDim.x + threadIdx.x;
    if (i < NN) g_dinv[i] = rsqrtf((float)g_pos[i] + 1.0f);
}

__global__ void scan1_kernel() {
    __shared__ int s[1024];
    int tid = threadIdx.x;
    int idx = blockIdx.x * 1024 + tid;
    int v = (idx < NN) ? g_pos[idx] : 0;
    s[tid] = v;
    __syncthreads();
    for (int off = 1; off < 1024; off <<= 1) {
        int t = (tid >= off) ? s[tid - off] : 0;
        __syncthreads();
        s[tid] += t;
        __syncthreads();
    }
    if (idx < NN) g_rowptr[idx] = s[tid] - v;
    if (tid == 1023) g_bsum[blockIdx.x] = s[1023];
}

__global__ void scan2_kernel() {
    __shared__ int s[128];
    int tid = threadIdx.x;
    int v = (tid < NSCAN_BLK) ? g_bsum[tid] : 0;
    s[tid] = v;
    __syncthreads();
    for (int off = 1; off < 128; off <<= 1) {
        int t = (tid >= off) ? s[tid - off] : 0;
        __syncthreads();
        s[tid] += t;
        __syncthreads();
    }
    if (tid < NSCAN_BLK) g_bsum[tid] = s[tid] - v;
    if (tid == 127) g_rowptr[NN] = s[127];
}

__global__ void scan3_kernel() {
    int idx = blockIdx.x * 1024 + threadIdx.x;
    if (idx < NN) {
        int r = g_rowptr[idx] + g_bsum[blockIdx.x];
        g_rowptr[idx] = r;
        g_pos[idx] = r;
    }
}

__global__ void csr_fill_kernel(const int* __restrict__ src, const int* __restrict__ dst) {
    int e = blockIdx.x * blockDim.x + threadIdx.x;
    if (e >= NE) return;
    int p = atomicAdd(&g_pos[dst[e]], 1);
    g_csrc[p] = src[e];
}

// ---------------- gather kernels (CSR, no atomics; 4x-coarsened) ----------------
__global__ void gather_add192_kernel(int xSel, const float* __restrict__ pe,
                                     int aggSel, int total) {
    int tid = blockIdx.x * blockDim.x + threadIdx.x;
    if (tid >= total) return;
    const float* x = scratch(xSel);
    float* agg = scratch(aggSel);
    int i = tid / 12;
    int t = tid - i * 12;
    int c0 = t * 4, c1 = (t + 12) * 4, c2 = (t + 24) * 4, c3 = (t + 36) * 4;
    int p0 = c0 & 63, p1 = c1 & 63, p2 = c2 & 63, p3 = c3 & 63;
    int beg = g_rowptr[i], end = g_rowptr[i + 1];
    float4 a0 = make_float4(0.f, 0.f, 0.f, 0.f), a1 = a0, a2 = a0, a3 = a0;
    for (int e = beg; e < end; e++) {
        int s = g_csrc[e];
        const float* xr = x + (size_t)s * 192;
        float4 v0 = *(const float4*)(xr + c0);
        float4 v1 = *(const float4*)(xr + c1);
        float4 v2 = *(const float4*)(xr + c2);
        float4 v3 = *(const float4*)(xr + c3);
        if (pe) {
            const float* pr = pe + (size_t)s * 64;
            float4 q0 = *(const float4*)(pr + p0);
            float4 q1 = *(const float4*)(pr + p1);
            float4 q2 = *(const float4*)(pr + p2);
            float4 q3 = *(const float4*)(pr + p3);
            v0.x += q0.x; v0.y += q0.y; v0.z += q0.z; v0.w += q0.w;
            v1.x += q1.x; v1.y += q1.y; v1.z += q1.z; v1.w += q1.w;
            v2.x += q2.x; v2.y += q2.y; v2.z += q2.z; v2.w += q2.w;
            v3.x += q3.x; v3.y += q3.y; v3.z += q3.z; v3.w += q3.w;
        }
        a0.x += v0.x; a0.y += v0.y; a0.z += v0.z; a0.w += v0.w;
        a1.x += v1.x; a1.y += v1.y; a1.z += v1.z; a1.w += v1.w;
        a2.x += v2.x; a2.y += v2.y; a2.z += v2.z; a2.w += v2.w;
        a3.x += v3.x; a3.y += v3.y; a3.z += v3.z; a3.w += v3.w;
    }
    float* ar = agg + (size_t)i * 192;
    *(float4*)(ar + c0) = a0;
    *(float4*)(ar + c1) = a1;
    *(float4*)(ar + c2) = a2;
    *(float4*)(ar + c3) = a3;
}

__global__ void gather_add32_kernel(const float* __restrict__ x, int aggSel, int total) {
    int tid = blockIdx.x * blockDim.x + threadIdx.x;
    if (tid >= total) return;
    float* agg = scratch(aggSel);
    int i = tid >> 2;
    int t = tid & 3;
    int c0 = t * 4, c1 = (t + 4) * 4;
    int beg = g_rowptr[i], end = g_rowptr[i + 1];
    float4 a0 = make_float4(0.f, 0.f, 0.f, 0.f), a1 = a0;
    for (int e = beg; e < end; e++) {
        int s = g_csrc[e];
        const float* xr = x + (size_t)s * 32;
        float4 v0 = *(const float4*)(xr + c0);
        float4 v1 = *(const float4*)(xr + c1);
        a0.x += v0.x; a0.y += v0.y; a0.z += v0.z; a0.w += v0.w;
        a1.x += v1.x; a1.y += v1.y; a1.z += v1.z; a1.w += v1.w;
    }
    float* ar = agg + (size_t)i * 32;
    *(float4*)(ar + c0) = a0;
    *(float4*)(ar + c1) = a1;
}

__global__ void gather_gcn_kernel(int hwSel, const float* __restrict__ b,
                                  int outSel, int add1Sel, int add2Sel, int total) {
    int tid = blockIdx.x * blockDim.x + threadIdx.x;
    if (tid >= total) return;
    const float* hw = scratch(hwSel);
    float* out = scratch(outSel);
    int i = tid / 12;
    int t = tid - i * 12;
    int beg = g_rowptr[i], end = g_rowptr[i + 1];
    float4 a[4];
#pragma unroll
    for (int j = 0; j < 4; j++) a[j] = make_float4(0.f, 0.f, 0.f, 0.f);
    for (int e = beg; e < end; e++) {
        int s = g_csrc[e];
        float w = g_dinv[s];
        const float* hr = hw + (size_t)s * 192;
#pragma unroll
        for (int j = 0; j < 4; j++) {
            float4 v = *(const float4*)(hr + (t + 12 * j) * 4);
            a[j].x += v.x * w; a[j].y += v.y * w; a[j].z += v.z * w; a[j].w += v.w * w;
        }
    }
    float di = g_dinv[i];
    float dii = di * di;
#pragma unroll
    for (int j = 0; j < 4; j++) {
        int c = (t + 12 * j) * 4;
        size_t idx = (size_t)i * 192 + c;
        float4 sv = *(const float4*)(hw + idx);
        float4 bb = *(const float4*)(b + c);
        float4 o;
        o.x = fmaxf(a[j].x * di + sv.x * dii + bb.x, 0.f);
        o.y = fmaxf(a[j].y * di + sv.y * dii + bb.y, 0.f);
        o.z = fmaxf(a[j].z * di + sv.z * dii + bb.z, 0.f);
        o.w = fmaxf(a[j].w * di + sv.w * dii + bb.w, 0.f);
        if (add1Sel >= 0) {
            float4 x1 = *(const float4*)(scratch(add1Sel) + idx);
            float4 x2 = *(const float4*)(scratch(add2Sel) + idx);
            o.x += x1.x + x2.x; o.y += x1.y + x2.y;
            o.z += x1.z + x2.z; o.w += x1.w + x2.w;
        }
        *(float4*)(out + idx) = o;
    }
}

__global__ void gather_gcn_bcast_kernel(int zgwSel, const int* __restrict__ batch,
                                        const float* __restrict__ b,
                                        int outSel, int total) {
    int tid = blockIdx.x * blockDim.x + threadIdx.x;
    if (tid >= total) return;
    const float* zgw = scratch(zgwSel);
    float* out = scratch(outSel);
    int i = tid / 12;
    int t = tid - i * 12;
    int beg = g_rowptr[i], end = g_rowptr[i + 1];
    float4 a[4];
#pragma unroll
    for (int j = 0; j < 4; j++) a[j] = make_float4(0.f, 0.f, 0.f, 0.f);
    for (int e = beg; e < end; e++) {
        int s = g_csrc[e];
        float w = g_dinv[s];
        const float* zr = zgw + (size_t)batch[s] * 192;
#pragma unroll
        for (int j = 0; j < 4; j++) {
            float4 v = *(const float4*)(zr + (t + 12 * j) * 4);
            a[j].x += v.x * w; a[j].y += v.y * w; a[j].z += v.z * w; a[j].w += v.w * w;
        }
    }
    float di = g_dinv[i];
    float dii = di * di;
    const float* zr = zgw + (size_t)batch[i] * 192;
#pragma unroll
    for (int j = 0; j < 4; j++) {
        int c = (t + 12 * j) * 4;
        float4 sv = *(const float4*)(zr + c);
        float4 bb = *(const float4*)(b + c);
        float4 o;
        o.x = fmaxf(a[j].x * di + sv.x * dii + bb.x, 0.f);
        o.y = fmaxf(a[j].y * di + sv.y * dii + bb.y, 0.f);
        o.z = fmaxf(a[j].z * di + sv.z * dii + bb.z, 0.f);
        o.w = fmaxf(a[j].w * di + sv.w * dii + bb.w, 0.f);
        *(float4*)(out + (size_t)i * 192 + c) = o;
    }
}

// ---------------- fused attention: one block per graph, thread = feature ----------------
__global__ void att_fused_kernel(int gateSel, int zSel) {
    int gph = blockIdx.x;
    int f = threadIdx.x;   // 0..191
    const float* gate = scratch(gateSel);
    const float* z = scratch(zSel);
    float* zg = scratch(SEL_ZG);
    int n0 = g_gstart[gph], n1 = g_gstart[gph + 1];
    if (n0 >= n1) { zg[gph * 192 + f] = 0.f; return; }

    float m0 = -FLT_MAX, m1 = -FLT_MAX, m2 = -FLT_MAX, m3 = -FLT_MAX;
    int n = n0;
    for (; n + 3 < n1; n += 4) {
        m0 = fmaxf(m0, gate[(size_t)(n + 0) * 192 + f]);
        m1 = fmaxf(m1, gate[(size_t)(n + 1) * 192 + f]);
        m2 = fmaxf(m2, gate[(size_t)(n + 2) * 192 + f]);
        m3 = fmaxf(m3, gate[(size_t)(n + 3) * 192 + f]);
    }
    for (; n < n1; n++) m0 = fmaxf(m0, gate[(size_t)n * 192 + f]);
    float m = fmaxf(fmaxf(m0, m1), fmaxf(m2, m3));

    float es0 = 0.f, es1 = 0.f, ez0 = 0.f, ez1 = 0.f;
    n = n0;
    for (; n + 1 < n1; n += 2) {
        size_t i0 = (size_t)n * 192 + f, i1 = (size_t)(n + 1) * 192 + f;
        float e0 = expf(gate[i0] - m);
        float e1 = expf(gate[i1] - m);
        es0 += e0; ez0 += e0 * z[i0];
        es1 += e1; ez1 += e1 * z[i1];
    }
    if (n < n1) {
        size_t i0 = (size_t)n * 192 + f;
        float e0 = expf(gate[i0] - m);
        es0 += e0; ez0 += e0 * z[i0];
    }
    zg[gph * 192 + f] = (ez0 + ez1) / (es0 + es1);
}

// ---------------- FP16 tensor-core GEMM (BM=256, BN=64, BK=16; mma.m16n8k16) --------
// fp16 operands (10-bit mantissa, same as tf32), fp32 accumulate.
// A smem: [256][12] uint32 (8 k-pairs + 4 pad) -> frag-load banks (12g+t4)%32 all distinct.
// B smem: [8][72] uint32 (k-pair x n)          -> frag-load banks (8t4+g)%32 all distinct.
__device__ __forceinline__ uint32_t pack_h2(float lo, float hi) {
    __half2 h = __floats2half2_rn(lo, hi);
    return *reinterpret_cast<uint32_t*>(&h);
}

__device__ __forceinline__ void mma_f16(float& c0, float& c1, float& c2, float& c3,
                                        uint32_t a0, uint32_t a1, uint32_t a2, uint32_t a3,
                                        uint32_t b0, uint32_t b1) {
    asm volatile(
        "mma.sync.aligned.m16n8k16.row.col.f32.f16.f16.f32 "
        "{%0,%1,%2,%3},{%4,%5,%6,%7},{%8,%9},{%0,%1,%2,%3};\n"
        : "+f"(c0), "+f"(c1), "+f"(c2), "+f"(c3)
        : "r"(a0), "r"(a1), "r"(a2), "r"(a3), "r"(b0), "r"(b1));
}

__global__ __launch_bounds__(256)
void tgemm_kernel(int M, int N, int K,
                  const float* __restrict__ Aext, int Asel,
                  const float* __restrict__ B,
                  const float* __restrict__ bias,
                  int resSel,
                  float* __restrict__ Cext, int Csel,
                  int relu) {
    __shared__ uint32_t As[256][12];  // k-pairs (16 halves = 8 pairs) + pad
    __shared__ uint32_t Bs[8][72];    // k-pair x n + pad

    const float* A = Aext ? Aext : scratch(Asel);
    float* C = Cext ? Cext : scratch(Csel);
    const float* res = (resSel >= 0) ? scratch(resSel) : nullptr;

    int tid = threadIdx.x;
    int bm0 = blockIdx.y * 256, bn0 = blockIdx.x * 64;
    int lane = tid & 31, wid = tid >> 5;
    int g = lane >> 2, t4 = lane & 3;
    int wm = (wid & 3) * 64;    // 4 warps down M
    int wn = (wid >> 2) * 32;   // 2 warps across N

    // A staging: 256 rows x 16 floats = 1024 float4, 4 per thread
    int aRow[4], aPc[4];
    bool aOk[4];
#pragma unroll
    for (int q = 0; q < 4; q++) {
        int fid = tid + 256 * q;
        aRow[q] = fid >> 2;
        aPc[q] = (fid & 3) << 1;           // k-pair index 0,2,4,6
        aOk[q] = (bm0 + aRow[q]) < M;
    }
    // B staging: 16 rows x 64 cols floats; thread packs 2 cols of one k-pair
    int bK2 = tid >> 5;                    // 0..7
    int bCol = (lane) << 1;                // 0..62
    const float* Bp0 = B + (size_t)(2 * bK2) * N + bn0 + bCol;
    const float* Bp1 = B + (size_t)(2 * bK2 + 1) * N + bn0 + bCol;

    float acc[4][4][4];
#pragma unroll
    for (int mi = 0; mi < 4; mi++)
#pragma unroll
        for (int ni = 0; ni < 4; ni++)
#pragma unroll
            for (int q = 0; q < 4; q++) acc[mi][ni][q] = 0.f;

    float4 pa[4];
#pragma unroll
    for (int q = 0; q < 4; q++) {
        pa[q] = make_float4(0.f, 0.f, 0.f, 0.f);
        if (aOk[q]) pa[q] = *(const float4*)(A + (size_t)(bm0 + aRow[q]) * K + (aPc[q] << 1));
    }
    float2 pb0 = *(const float2*)Bp0;
    float2 pb1 = *(const float2*)Bp1;

    for (int k0 = 0; k0 < K; k0 += 16) {
#pragma unroll
        for (int q = 0; q < 4; q++) {
            As[aRow[q]][aPc[q] + 0] = pack_h2(pa[q].x, pa[q].y);
            As[aRow[q]][aPc[q] + 1] = pack_h2(pa[q].z, pa[q].w);
        }
        Bs[bK2][bCol + 0] = pack_h2(pb0.x, pb1.x);
        Bs[bK2][bCol + 1] = pack_h2(pb0.y, pb1.y);
        __syncthreads();

        if (k0 + 16 < K) {
#pragma unroll
            for (int q = 0; q < 4; q++)
                if (aOk[q]) pa[q] = *(const float4*)(A + (size_t)(bm0 + aRow[q]) * K + k0 + 16 + (aPc[q] << 1));
            pb0 = *(const float2*)(Bp0 + (size_t)(k0 + 16) * N);
            pb1 = *(const float2*)(Bp1 + (size_t)(k0 + 16) * N);
        }

        uint32_t af[4][4], bf[4][2];
#pragma unroll
        for (int mi = 0; mi < 4; mi++) {
            int rb = wm + mi * 16;
            af[mi][0] = As[rb + g][t4];
            af[mi][1] = As[rb + g + 8][t4];
            af[mi][2] = As[rb + g][t4 + 4];
            af[mi][3] = As[rb + g + 8][t4 + 4];
        }
#pragma unroll
        for (int ni = 0; ni < 4; ni++) {
            int cb = wn + ni * 8 + g;
            bf[ni][0] = Bs[t4][cb];
            bf[ni][1] = Bs[t4 + 4][cb];
        }
#pragma unroll
        for (int mi = 0; mi < 4; mi++)
#pragma unroll
            for (int ni = 0; ni < 4; ni++)
                mma_f16(acc[mi][ni][0], acc[mi][ni][1], acc[mi][ni][2], acc[mi][ni][3],
                        af[mi][0], af[mi][1], af[mi][2], af[mi][3],
                        bf[ni][0], bf[ni][1]);
        __syncthreads();
    }

#pragma unroll
    for (int mi = 0; mi < 4; mi++) {
#pragma unroll
        for (int ni = 0; ni < 4; ni++) {
            int col = bn0 + wn + ni * 8 + 2 * t4;
            float bx = bias ? bias[col] : 0.f;
            float by = bias ? bias[col + 1] : 0.f;
#pragma unroll
            for (int h = 0; h < 2; h++) {
                int r = bm0 + wm + mi * 16 + g + h * 8;
                if (r >= M) continue;
                float v0 = acc[mi][ni][2 * h + 0] + bx;
                float v1 = acc[mi][ni][2 * h + 1] + by;
                if (relu) { v0 = fmaxf(v0, 0.f); v1 = fmaxf(v1, 0.f); }
                if (res) {
                    v0 += res[(size_t)r * N + col];
                    v1 += res[(size_t)r * N + col + 1];
                }
                *(float2*)(C + (size_t)r * N + col) = make_float2(v0, v1);
            }
        }
    }
}

// ---------------- launch helpers ----------------
static inline void launch_gemm(int M, int N, int K,
                               const float* Aext, int Asel, const float* B,
                               const float* bias, int resSel,
                               float* Cext, int Csel, int relu) {
    dim3 grid((N + 63) / 64, (M + 255) / 256);
    tgemm_kernel<<<grid, 256>>>(M, N, K, Aext, Asel, B, bias, resSel, Cext, Csel, relu);
}

extern "C" void kernel_launch(void* const* d_in, const int* in_sizes, int n_in,
                              void* d_out, int out_size) {
    const float* x1    = (const float*)d_in[0];
    const float* x2    = (const float*)d_in[1];
    const float* pe    = (const float*)d_in[2];
    const int*   ei    = (const int*)d_in[3];
    const int*   batch = (const int*)d_in[4];
    const float *Wc  = (const float*)d_in[5],  *bc  = (const float*)d_in[6];
    const float *Wmf = (const float*)d_in[7],  *bmf = (const float*)d_in[8];
    const float *Wgf = (const float*)d_in[9],  *bgf = (const float*)d_in[10];
    const float *Wmc = (const float*)d_in[11], *bmc = (const float*)d_in[12];
    const float *Wgc = (const float*)d_in[13], *bgc = (const float*)d_in[14];
    const float *Wa1 = (const float*)d_in[15], *ba1 = (const float*)d_in[16];
    const float *Wa2 = (const float*)d_in[17], *ba2 = (const float*)d_in[18];
    const float *Wgd = (const float*)d_in[19], *bgd = (const float*)d_in[20];
    const float *Wd1 = (const float*)d_in[21], *bd1 = (const float*)d_in[22];
    const float *Wd2 = (const float*)d_in[23], *bd2 = (const float*)d_in[24];
    const float *Wd3 = (const float*)d_in[25], *bd3 = (const float*)d_in[26];
    float* out = (float*)d_out;

    const int* src = ei;
    const int* dst = ei + NE;

    const int NODE192 = NN * 12;   // 12 threads/node (4x coarsened)
    const int NODE32  = NN * 4;    // 4 threads/node
    const int BLK = 256;

    // ---- CSR build + graph segment bounds ----
    zero_pos_kernel<<<(NN + BLK - 1) / BLK, BLK>>>();
    gstart_kernel<<<1, NG + 1>>>(batch);
    count_deg_kernel<<<(NE + BLK - 1) / BLK, BLK>>>(dst);
    dinv_kernel<<<(NN + BLK - 1) / BLK, BLK>>>();
    scan1_kernel<<<NSCAN_BLK, 1024>>>();
    scan2_kernel<<<1, 128>>>();
    scan3_kernel<<<NSCAN_BLK, 1024>>>();
    csr_fill_kernel<<<(NE + BLK - 1) / BLK, BLK>>>(src, dst);

    // ---- encoder ----
    launch_gemm(NN, 192, 384, x1, -1, Wc, bc, -1, nullptr, 0, 1);
    gather_add192_kernel<<<(NODE192 + BLK - 1) / BLK, BLK>>>(0, pe, 1, NODE192);
    launch_gemm(NN, 256, 192, nullptr, 1, Wmf, bmf, -1, nullptr, 2, 1);
    launch_gemm(NN, 192, 256, nullptr, 2, Wgf, nullptr, -1, nullptr, 3, 0);
    gather_gcn_kernel<<<(NODE192 + BLK - 1) / BLK, BLK>>>(3, bgf, 4, -1, -1, NODE192);
    gather_add32_kernel<<<(NODE32 + BLK - 1) / BLK, BLK>>>(x2, 1, NODE32);
    launch_gemm(NN, 64, 32, nullptr, 1, Wmc, bmc, -1, nullptr, 2, 1);
    launch_gemm(NN, 192, 64, nullptr, 2, Wgc, nullptr, -1, nullptr, 3, 0);
    // z = relu(gcn_c) + h2 + x1res  (fused) -> B4
    gather_gcn_kernel<<<(NODE192 + BLK - 1) / BLK, BLK>>>(3, bgc, 4, 4, 0, NODE192);

    // ---- attentional aggregation (atomic-free) ----
    launch_gemm(NN, 256, 192, nullptr, 4, Wa1, ba1, -1, nullptr, 2, 1);
    launch_gemm(NN, 192, 256, nullptr, 2, Wa2, ba2, -1, nullptr, 3, 0);
    att_fused_kernel<<<NG, 192>>>(3, 4);

    // ---- decoder ----
    launch_gemm(NG, 192, 192, nullptr, SEL_ZG, Wgd, nullptr, -1, nullptr, SEL_ZGW, 0);
    gather_gcn_bcast_kernel<<<(NODE192 + BLK - 1) / BLK, BLK>>>(SEL_ZGW, batch, bgd, 5, NODE192);
    gather_add192_kernel<<<(NODE192 + BLK - 1) / BLK, BLK>>>(5, pe, 1, NODE192);
    launch_gemm(NN, 192, 192, nullptr, 1, Wd1, bd1, -1, nullptr, 2, 1);
    gather_add192_kernel<<<(NODE192 + BLK - 1) / BLK, BLK>>>(2, nullptr, 1, NODE192);
    launch_gemm(NN, 192, 192, nullptr, 1, Wd2, bd2, 5, nullptr, 3, 1);
    gather_add192_kernel<<<(NODE192 + BLK - 1) / BLK, BLK>>>(3, nullptr, 1, NODE192);
    launch_gemm(NN, 384, 192, nullptr, 1, Wd3, bd3, -1, out, -1, 1);
}